// round 7
// baseline (speedup 1.0000x reference)
#include <cuda_runtime.h>

// CLUBLoss, two-pass, 2-launch version.
//   x        : (B=16, D=512, H=32, W=32) f32
//   p_mu     : (N=16384, D=512) f32,  n = b*H*W + h*W + w
//   p_logvar : (N=16384, D=512) f32
//
// loss_i = -0.5 * sum_d [ (x^2 - m2_d) - 2*mu*(x - m1_d) ] * exp(-lv)
// out    = mean_i loss_i
// Pass 1 writes per-half raw column sums (no atomics, no zero pass).
// Pass 2 accumulates g_A and the LAST block writes the final scalar.

#define DI      512
#define BB      16
#define HH      32
#define WW      32
#define NN      (BB * HH * WW)
#define SPATIAL (HH * WW)
#define DH      128
#define NBLK2   2048   // 512 (b,h) tiles * 4 d-quarters

__device__ float g_m1p[2][DI];   // raw column sums, per batch-half
__device__ float g_m2p[2][DI];
__device__ float g_A;
__device__ unsigned int g_count;

// ---------------------------------------------------------------------------
// Pass 1: grid 1024 = (d, batch-half). Block reduces 8 batches x 1024 floats
// for one d: 2048 float4 / 256 threads = 8 LDG.128 per thread, unrolled.
// Direct partial writes -> no atomics -> no zero kernel.
// Block 0 also resets g_A / g_count for pass 2 (stream-ordered).
// ---------------------------------------------------------------------------
__global__ void __launch_bounds__(256) colstats_kernel(const float* __restrict__ x) {
    const int t    = threadIdx.x;
    const int d    = blockIdx.x >> 1;
    const int half = blockIdx.x & 1;

    if (blockIdx.x == 0 && t == 0) { g_A = 0.f; g_count = 0u; }

    const float4* base = (const float4*)(x + (size_t)(half * 8) * (DI * SPATIAL)
                                           + (size_t)d * SPATIAL);
    float s1 = 0.f, s2 = 0.f;
    #pragma unroll
    for (int k = 0; k < 8; ++k) {
        const int i  = t + k * 256;           // 0..2047
        const int bl = i >> 8;                // batch within half (0..7)
        const int s  = i & 255;               // float4 within 1024-float chunk
        const float4 v = base[(size_t)bl * (DI * SPATIAL / 4) + s];
        s1 += v.x + v.y + v.z + v.w;
        s2 += v.x * v.x + v.y * v.y + v.z * v.z + v.w * v.w;
    }
    __shared__ float sh1[256], sh2[256];
    sh1[t] = s1;
    sh2[t] = s2;
    __syncthreads();
    for (int off = 128; off > 0; off >>= 1) {
        if (t < off) {
            sh1[t] += sh1[t + off];
            sh2[t] += sh2[t + off];
        }
        __syncthreads();
    }
    if (t == 0) {
        g_m1p[half][d] = sh1[0];
        g_m2p[half][d] = sh2[0];
    }
}

// ---------------------------------------------------------------------------
// Pass 2: fused loss + in-kernel finalization.
// Block = one (b,h) pair (32 tokens) x 128 d-columns. x slab staged via smem;
// thread t owns d-quad dq=t&31 and 4 tokens (wg=t>>5); all 8 mu/lv LDG.128
// batched -> MLP 8. Per-element cancellation keeps accumulands O(1).
// Last block (ticket) writes out = g_A * (-0.5/N).
// ---------------------------------------------------------------------------
__global__ void __launch_bounds__(256) loss_kernel(const float* __restrict__ x,
                                                   const float* __restrict__ mu,
                                                   const float* __restrict__ lv,
                                                   float* __restrict__ out) {
    const int bh    = blockIdx.x >> 2;    // b*32 + h
    const int dpart = blockIdx.x & 3;
    const int b     = bh >> 5;
    const int h     = bh & 31;
    const int doff  = dpart * DH;
    const int n0    = bh * WW;

    __shared__ float xs[WW * 132];        // [w*132 + d_local], 16.9 KB
    __shared__ float m1s[DH], m2s[DH];
    float* redA = xs;                     // aliased after compute

    const int t  = threadIdx.x;
    const int dq = t & 31;
    const int wg = t >> 5;
    const int d0 = dq * 4;

    if (t < DH) {
        const int d = doff + t;
        m1s[t] = (g_m1p[0][d] + g_m1p[1][d]) * (1.0f / NN);
        m2s[t] = (g_m2p[0][d] + g_m2p[1][d]) * (1.0f / NN);
    }

    // stage x slab: 128 d-rows x 8 float4 = 1024 float4, 4 per thread
    const float4* xbase = (const float4*)(x + (size_t)b * (DI * SPATIAL)
                                            + (size_t)doff * SPATIAL
                                            + (size_t)h * WW);
    #pragma unroll
    for (int it = 0; it < 4; ++it) {
        const int i  = t + it * 256;
        const int dr = i >> 3;
        const int q  = i & 7;
        const float4 v = xbase[(size_t)dr * (SPATIAL / 4) + q];
        float* row = &xs[(q * 4) * 132 + dr];
        row[0 * 132] = v.x; row[1 * 132] = v.y;
        row[2 * 132] = v.z; row[3 * 132] = v.w;
    }
    __syncthreads();

    const float4 m1v = *(const float4*)&m1s[d0];
    const float4 m2v = *(const float4*)&m2s[d0];

    // batch all 4 tokens' mu/lv: 8 LDG.128 in flight
    const size_t rbase = ((size_t)(n0 + wg * 4) * DI + doff) / 4 + dq;
    float4 m[4], l[4];
    #pragma unroll
    for (int k = 0; k < 4; ++k) {
        m[k] = ((const float4*)mu)[rbase + (size_t)k * (DI / 4)];
        l[k] = ((const float4*)lv)[rbase + (size_t)k * (DI / 4)];
    }

    float acc = 0.f;
    #pragma unroll
    for (int k = 0; k < 4; ++k) {
        const int w = wg * 4 + k;
        const float* xr = &xs[w * 132 + d0];
        const float vx = xr[0], vy = xr[1], vz = xr[2], vw = xr[3];
        acc += ((vx * vx - m2v.x) - 2.0f * m[k].x * (vx - m1v.x)) * __expf(-l[k].x);
        acc += ((vy * vy - m2v.y) - 2.0f * m[k].y * (vy - m1v.y)) * __expf(-l[k].y);
        acc += ((vz * vz - m2v.z) - 2.0f * m[k].z * (vz - m1v.z)) * __expf(-l[k].z);
        acc += ((vw * vw - m2v.w) - 2.0f * m[k].w * (vw - m1v.w)) * __expf(-l[k].w);
    }

    __syncthreads();     // done reading xs
    redA[t] = acc;
    __syncthreads();
    for (int off = 128; off > 0; off >>= 1) {
        if (t < off) redA[t] += redA[t + off];
        __syncthreads();
    }

    if (t == 0) {
        atomicAdd(&g_A, redA[0]);
        __threadfence();
        const unsigned int ticket = atomicAdd(&g_count, 1u);
        if (ticket == NBLK2 - 1) {
            // all blocks' g_A contributions are fenced-visible
            out[0] = *((volatile float*)&g_A) * (-0.5f / (float)NN);
        }
    }
}

extern "C" void kernel_launch(void* const* d_in, const int* in_sizes, int n_in,
                              void* d_out, int out_size) {
    const float* x  = (const float*)d_in[0];
    const float* mu = (const float*)d_in[1];
    const float* lv = (const float*)d_in[2];
    float* out = (float*)d_out;

    colstats_kernel<<<1024, 256>>>(x);
    loss_kernel<<<NBLK2, 256>>>(x, mu, lv, out);
}